// round 2
// baseline (speedup 1.0000x reference)
#include <cuda_runtime.h>
#include <math.h>

// ---------------- problem constants (fixed instance) ----------------
#define B_ 8
#define S_ 4096
#define D_ 768
#define D4_ (D_/4)
#define NIMG_ 1024
#define FF_ 3072
#define CAP_ 640
#define H_ 12
#define DH_ 64
#define ROWS_ (B_*CAP_)      // 5120
#define IMGROWS_ (B_*NIMG_)  // 8192
#define SOC_TOK 3
#define EOS_TOK 2
#define LN_EPS 1e-5f

// ---------------- device scratch (no allocations allowed) ----------------
// Referenced directly by symbol in device code — no cudaGetSymbolAddress on host.
__device__ float g_x [ROWS_*D_];         // running hidden x  [B,CAP,D]
__device__ float g_y [ROWS_*D_];         // LN output
__device__ float g_q [ROWS_*D_];         // Q projections
__device__ float g_k [IMGROWS_*D_];      // K projections (self uses first 5120 rows)
__device__ float g_v [IMGROWS_*D_];      // V projections
__device__ float g_ao[ROWS_*D_];         // attention output
__device__ float g_h [ROWS_*FF_];        // FFN hidden
__device__ int   g_pos[B_*S_];           // slot per token, -1 if not SOC
__device__ int   g_cnt[B_];              // SOC counts per batch

// ---------------- scan: soc mask + exclusive prefix ----------------
__global__ void scan_kernel(const int* __restrict__ seq)
{
    int b = blockIdx.x;
    const int* row = seq + b*S_;
    __shared__ int firstEos;
    __shared__ int wsum[32];
    if (threadIdx.x == 0) firstEos = S_;
    __syncthreads();
    for (int s = threadIdx.x; s < S_; s += blockDim.x)
        if (row[s] == EOS_TOK) atomicMin(&firstEos, s);
    __syncthreads();
    int fe = firstEos;
    int base = threadIdx.x * 4;
    int m[4]; int cnt = 0;
    #pragma unroll
    for (int i = 0; i < 4; i++) {
        int s = base + i;
        m[i] = (row[s] == SOC_TOK && s < fe) ? 1 : 0;
        cnt += m[i];
    }
    int lane = threadIdx.x & 31, w = threadIdx.x >> 5;
    int v = cnt;
    #pragma unroll
    for (int o = 1; o < 32; o <<= 1) {
        int n = __shfl_up_sync(0xffffffffu, v, o);
        if (lane >= o) v += n;
    }
    if (lane == 31) wsum[w] = v;
    __syncthreads();
    if (w == 0) {
        int t = wsum[lane];
        #pragma unroll
        for (int o = 1; o < 32; o <<= 1) {
            int n = __shfl_up_sync(0xffffffffu, t, o);
            if (lane >= o) t += n;
        }
        wsum[lane] = t;
    }
    __syncthreads();
    int excl = v - cnt + (w ? wsum[w-1] : 0);
    int* prow = g_pos + b*S_;
    #pragma unroll
    for (int i = 0; i < 4; i++) {
        prow[base+i] = m[i] ? excl : -1;
        excl += m[i];
    }
    if (threadIdx.x == 0) g_cnt[b] = wsum[31];
}

// ---------------- zero x, then gather SOC rows ----------------
__global__ void zero_x_kernel()
{
    int i = blockIdx.x*blockDim.x + threadIdx.x;
    if (i < ROWS_*D4_) ((float4*)g_x)[i] = make_float4(0.f,0.f,0.f,0.f);
}

__global__ void extract_kernel(const float* __restrict__ hid)  // grid (S_, B_), block 192
{
    int s = blockIdx.x, b = blockIdx.y;
    int p = g_pos[b*S_ + s];
    if (p < 0 || p >= CAP_) return;
    const float4* src = (const float4*)(hid + ((size_t)(b*S_+s))*D_);
    float4* dst = (float4*)(g_x + ((size_t)(b*CAP_+p))*D_);
    dst[threadIdx.x] = src[threadIdx.x];
}

// ---------------- LayerNorm: one row per block (g_x -> g_y) ----------------
__global__ void ln_kernel(const float* __restrict__ sc, const float* __restrict__ bi)
{
    int r = blockIdx.x;
    const float* x = g_x + (size_t)r*D_;
    float s1 = 0.f, s2 = 0.f;
    for (int d = threadIdx.x; d < D_; d += blockDim.x) {
        float v = x[d]; s1 += v; s2 += v*v;
    }
    #pragma unroll
    for (int o = 16; o > 0; o >>= 1) {
        s1 += __shfl_xor_sync(0xffffffffu, s1, o);
        s2 += __shfl_xor_sync(0xffffffffu, s2, o);
    }
    __shared__ float a1[8], a2[8];
    int w = threadIdx.x >> 5, l = threadIdx.x & 31;
    if (l == 0) { a1[w] = s1; a2[w] = s2; }
    __syncthreads();
    if (threadIdx.x == 0) {
        float t1 = 0.f, t2 = 0.f;
        #pragma unroll
        for (int i = 0; i < 8; i++) { t1 += a1[i]; t2 += a2[i]; }
        a1[0] = t1; a2[0] = t2;
    }
    __syncthreads();
    float mu  = a1[0] * (1.f/(float)D_);
    float var = a2[0] * (1.f/(float)D_) - mu*mu;
    float rs  = rsqrtf(var + LN_EPS);
    float* o = g_y + (size_t)r*D_;
    for (int d = threadIdx.x; d < D_; d += blockDim.x)
        o[d] = (x[d]-mu)*rs*sc[d] + bi[d];
}

// ---------------- GELU (tanh approx, matches jax default) ----------------
__device__ __forceinline__ float gelu_f(float v)
{
    const float c = 0.7978845608028654f;   // sqrt(2/pi)
    float inner = c*(v + 0.044715f*v*v*v);
    return 0.5f*v*(1.f + tanhf(inner));
}

// ---------------- SGEMM body: C[M,N] (+)= A[M,K] @ W[K,N], 128x128x8 tiles ----------------
template<bool ACC, bool GELU>
__device__ __forceinline__ void sgemm_body(
    const float* __restrict__ A, const float* __restrict__ W,
    float* __restrict__ C, int N, int K)
{
    __shared__ float As[8][132];   // padded: conflict-free transposed stores/reads
    __shared__ float Bs[8][128];
    const int tid = threadIdx.x;
    const int bm = blockIdx.y * 128, bn = blockIdx.x * 128;
    const int w = tid >> 5, l = tid & 31;
    const int r0 = (w >> 2)*64 + (l >> 2)*4;
    const int r1 = r0 + 32;
    const int c0 = (w & 3)*32 + (l & 3)*4;
    const int c1 = c0 + 16;
    float acc[8][8];
    #pragma unroll
    for (int i = 0; i < 8; i++)
        #pragma unroll
        for (int j = 0; j < 8; j++) acc[i][j] = 0.f;

    const int ar = tid >> 1, kc = (tid & 1)*4;
    const int br = tid >> 5, bc = (tid & 31)*4;
    const float* Ap = A + (size_t)(bm + ar)*K + kc;
    const float* Wp = W + (size_t)br*N + bn + bc;
    float4 a  = *(const float4*)Ap;
    float4 bv = *(const float4*)Wp;

    for (int k0 = 0; k0 < K; k0 += 8) {
        As[kc+0][ar] = a.x; As[kc+1][ar] = a.y; As[kc+2][ar] = a.z; As[kc+3][ar] = a.w;
        *(float4*)&Bs[br][bc] = bv;
        __syncthreads();
        float4 an = a, bn2 = bv;
        if (k0 + 8 < K) {
            an  = *(const float4*)(Ap + k0 + 8);
            bn2 = *(const float4*)(Wp + (size_t)(k0+8)*N);
        }
        #pragma unroll
        for (int kk = 0; kk < 8; kk++) {
            float4 a0 = *(const float4*)&As[kk][r0];
            float4 a1 = *(const float4*)&As[kk][r1];
            float4 b0 = *(const float4*)&Bs[kk][c0];
            float4 b1 = *(const float4*)&Bs[kk][c1];
            float av[8] = {a0.x,a0.y,a0.z,a0.w,a1.x,a1.y,a1.z,a1.w};
            float bw[8] = {b0.x,b0.y,b0.z,b0.w,b1.x,b1.y,b1.z,b1.w};
            #pragma unroll
            for (int i = 0; i < 8; i++)
                #pragma unroll
                for (int j = 0; j < 8; j++)
                    acc[i][j] = fmaf(av[i], bw[j], acc[i][j]);
        }
        __syncthreads();
        a = an; bv = bn2;
    }
    #pragma unroll
    for (int ri = 0; ri < 2; ri++) {
        int rb = ri ? r1 : r0;
        #pragma unroll
        for (int i = 0; i < 4; i++) {
            size_t rowoff = (size_t)(bm + rb + i)*N + bn;
            #pragma unroll
            for (int ci = 0; ci < 2; ci++) {
                int cc = ci ? c1 : c0;
                float* cp = C + rowoff + cc;
                float v0 = acc[ri*4+i][ci*4+0];
                float v1 = acc[ri*4+i][ci*4+1];
                float v2 = acc[ri*4+i][ci*4+2];
                float v3 = acc[ri*4+i][ci*4+3];
                if (GELU) { v0 = gelu_f(v0); v1 = gelu_f(v1); v2 = gelu_f(v2); v3 = gelu_f(v3); }
                float4 o;
                if (ACC) {
                    float4 old = *(const float4*)cp;
                    o = make_float4(old.x+v0, old.y+v1, old.z+v2, old.w+v3);
                } else {
                    o = make_float4(v0, v1, v2, v3);
                }
                *(float4*)cp = o;
            }
        }
    }
}

// Wrapper kernels: scratch buffers named directly (no host symbol lookup).
__global__ void __launch_bounds__(256) gemm_y_q (const float* __restrict__ W){ sgemm_body<false,false>(g_y,  W, g_q,  D_,  D_ ); }
__global__ void __launch_bounds__(256) gemm_y_k (const float* __restrict__ W){ sgemm_body<false,false>(g_y,  W, g_k,  D_,  D_ ); }
__global__ void __launch_bounds__(256) gemm_y_v (const float* __restrict__ W){ sgemm_body<false,false>(g_y,  W, g_v,  D_,  D_ ); }
__global__ void __launch_bounds__(256) gemm_img_k(const float* __restrict__ A, const float* __restrict__ W){ sgemm_body<false,false>(A, W, g_k, D_, D_); }
__global__ void __launch_bounds__(256) gemm_img_v(const float* __restrict__ A, const float* __restrict__ W){ sgemm_body<false,false>(A, W, g_v, D_, D_); }
__global__ void __launch_bounds__(256) gemm_ao_x(const float* __restrict__ W){ sgemm_body<true, false>(g_ao, W, g_x,  D_,  D_ ); }
__global__ void __launch_bounds__(256) gemm_y_h (const float* __restrict__ W){ sgemm_body<false,true >(g_y,  W, g_h,  FF_, D_ ); }
__global__ void __launch_bounds__(256) gemm_h_x (const float* __restrict__ W){ sgemm_body<true, false>(g_h,  W, g_x,  D_,  FF_); }

// ---------------- flash attention (fp32, online softmax) ----------------
// grid (CAP_/64, H_, B_), block 256. 64 queries/block, 4 threads per query.
template<bool MASK>
__device__ __forceinline__ void flash_body(int Lk)
{
    const int q0 = blockIdx.x * 64;
    const int h  = blockIdx.y;
    const int b  = blockIdx.z;
    const int tid = threadIdx.x;
    const int qi = tid >> 2;
    const int g  = tid & 3;

    __shared__ float Ks[64][68];
    __shared__ float Vs[64][68];
    float (*Ps)[68] = Ks;          // P tile reuses K tile storage

    float qreg[DH_];
    {
        const float* qp = g_q + ((size_t)(b*CAP_ + q0 + qi))*D_ + h*DH_;
        #pragma unroll
        for (int i = 0; i < DH_/4; i++) {
            float4 t = *(const float4*)(qp + 4*i);
            qreg[4*i]=t.x; qreg[4*i+1]=t.y; qreg[4*i+2]=t.z; qreg[4*i+3]=t.w;
        }
    }
    float Oacc[16];
    #pragma unroll
    for (int t = 0; t < 16; t++) Oacc[t] = 0.f;
    float mrun = -1e30f, lrun = 0.f;
    const int cnt = MASK ? g_cnt[b] : Lk;

    const int kr = tid >> 2;
    const int cb = (tid & 3) * 16;

    for (int k0 = 0; k0 < Lk; k0 += 64) {
        const float* kp = g_k + ((size_t)(b*Lk + k0 + kr))*D_ + h*DH_ + cb;
        const float* vp = g_v + ((size_t)(b*Lk + k0 + kr))*D_ + h*DH_ + cb;
        #pragma unroll
        for (int i = 0; i < 4; i++) {
            *(float4*)&Ks[kr][cb + 4*i] = *(const float4*)(kp + 4*i);
            *(float4*)&Vs[kr][cb + 4*i] = *(const float4*)(vp + 4*i);
        }
        __syncthreads();
        float s[16];
        #pragma unroll
        for (int j = 0; j < 16; j++) {
            int kj = 4*j + g;
            const float* krow = &Ks[kj][0];
            float acc = 0.f;
            #pragma unroll
            for (int d = 0; d < DH_; d += 4) {
                float4 kv = *(const float4*)(krow + d);
                acc = fmaf(qreg[d],   kv.x, acc);
                acc = fmaf(qreg[d+1], kv.y, acc);
                acc = fmaf(qreg[d+2], kv.z, acc);
                acc = fmaf(qreg[d+3], kv.w, acc);
            }
            acc *= 0.125f;  // 1/sqrt(64)
            if (MASK && (k0 + kj) >= cnt) acc = -1e9f;
            s[j] = acc;
        }
        float mx = s[0];
        #pragma unroll
        for (int j = 1; j < 16; j++) mx = fmaxf(mx, s[j]);
        mx = fmaxf(mx, __shfl_xor_sync(0xffffffffu, mx, 1));
        mx = fmaxf(mx, __shfl_xor_sync(0xffffffffu, mx, 2));
        float mnew = fmaxf(mrun, mx);
        float corr = expf(mrun - mnew);
        float lsum = 0.f;
        #pragma unroll
        for (int j = 0; j < 16; j++) { float p = expf(s[j]-mnew); s[j] = p; lsum += p; }
        lsum += __shfl_xor_sync(0xffffffffu, lsum, 1);
        lsum += __shfl_xor_sync(0xffffffffu, lsum, 2);
        lrun = lrun*corr + lsum;
        mrun = mnew;
        __syncthreads();                 // everyone done reading Ks (scores)
        #pragma unroll
        for (int j = 0; j < 16; j++) Ps[qi][4*j+g] = s[j];
        #pragma unroll
        for (int t = 0; t < 16; t++) Oacc[t] *= corr;
        __syncthreads();                 // Ps visible
        #pragma unroll
        for (int kk = 0; kk < 64; kk += 4) {
            float4 p4 = *(const float4*)&Ps[qi][kk];
            float pv[4] = {p4.x, p4.y, p4.z, p4.w};
            #pragma unroll
            for (int u = 0; u < 4; u++) {
                const float* vrow = &Vs[kk+u][cb];
                #pragma unroll
                for (int t = 0; t < 16; t += 4) {
                    float4 vv = *(const float4*)(vrow + t);
                    Oacc[t]   = fmaf(pv[u], vv.x, Oacc[t]);
                    Oacc[t+1] = fmaf(pv[u], vv.y, Oacc[t+1]);
                    Oacc[t+2] = fmaf(pv[u], vv.z, Oacc[t+2]);
                    Oacc[t+3] = fmaf(pv[u], vv.w, Oacc[t+3]);
                }
            }
        }
        __syncthreads();                 // done with Ps/Vs before next tile load
    }
    float inv = 1.f / lrun;
    float* op = g_ao + ((size_t)(b*CAP_ + q0 + qi))*D_ + h*DH_ + cb;
    #pragma unroll
    for (int t = 0; t < 16; t += 4) {
        float4 v;
        v.x = Oacc[t]*inv; v.y = Oacc[t+1]*inv; v.z = Oacc[t+2]*inv; v.w = Oacc[t+3]*inv;
        *(float4*)(op + t) = v;
    }
}

__global__ void __launch_bounds__(256) flash_self_kernel () { flash_body<true >(CAP_);  }
__global__ void __launch_bounds__(256) flash_cross_kernel() { flash_body<false>(NIMG_); }

// ---------------- outputs ----------------
__global__ void write_out_kernel(const float* __restrict__ hid, float* __restrict__ out)
{
    int i = blockIdx.x*blockDim.x + threadIdx.x;
    if (i >= B_*S_*D4_) return;
    int row = i / D4_;
    int d4  = i - row*D4_;
    int p = g_pos[row];
    float4 v;
    if (p >= 0) {
        int b = row >> 12;                  // row / S_
        int q = p < CAP_ ? p : (CAP_-1);    // reference clips idx to cap-1
        v = ((const float4*)g_x)[(size_t)(b*CAP_+q)*D4_ + d4];
    } else {
        v = ((const float4*)hid)[i];
    }
    ((float4*)out)[i] = v;
}

__global__ void copy_x_kernel(float* __restrict__ out)
{
    int i = blockIdx.x*blockDim.x + threadIdx.x;
    if (i < ROWS_*D4_) ((float4*)out)[i] = ((const float4*)g_x)[i];
}

// ---------------- launch: pure kernel launches, nothing else ----------------
extern "C" void kernel_launch(void* const* d_in, const int* in_sizes, int n_in,
                              void* d_out, int out_size)
{
    const float* img   = (const float*)d_in[0];
    const float* hid   = (const float*)d_in[1];
    const int*   seq   = (const int*)  d_in[2];
    const float* wq_s  = (const float*)d_in[3];
    const float* wk_s  = (const float*)d_in[4];
    const float* wv_s  = (const float*)d_in[5];
    const float* wo_s  = (const float*)d_in[6];
    const float* wq_c  = (const float*)d_in[7];
    const float* wk_c  = (const float*)d_in[8];
    const float* wv_c  = (const float*)d_in[9];
    const float* wo_c  = (const float*)d_in[10];
    const float* w_ff1 = (const float*)d_in[11];
    const float* w_ff2 = (const float*)d_in[12];
    const float* ln1_s = (const float*)d_in[13];
    const float* ln1_b = (const float*)d_in[14];
    const float* ln2_s = (const float*)d_in[15];
    const float* ln2_b = (const float*)d_in[16];
    const float* ln3_s = (const float*)d_in[17];
    const float* ln3_b = (const float*)d_in[18];
    float* out = (float*)d_out;

    // mask + extract
    scan_kernel<<<B_, 1024>>>(seq);
    zero_x_kernel<<<(ROWS_*D4_ + 255)/256, 256>>>();
    extract_kernel<<<dim3(S_, B_), 192>>>(hid);

    dim3 gP(D_/128, ROWS_/128);       // 6 x 40
    dim3 gI(D_/128, IMGROWS_/128);    // 6 x 64
    dim3 gF(FF_/128, ROWS_/128);      // 24 x 40
    dim3 gAtt(CAP_/64, H_, B_);       // 10 x 12 x 8

    // --- block 1: self-attention ---
    ln_kernel<<<ROWS_, 256>>>(ln1_s, ln1_b);
    gemm_y_q<<<gP, 256>>>(wq_s);
    gemm_y_k<<<gP, 256>>>(wk_s);
    gemm_y_v<<<gP, 256>>>(wv_s);
    flash_self_kernel<<<gAtt, 256>>>();
    gemm_ao_x<<<gP, 256>>>(wo_s);                 // x += ao@wo_s

    // --- block 2: cross-attention to img ---
    ln_kernel<<<ROWS_, 256>>>(ln2_s, ln2_b);
    gemm_y_q<<<gP, 256>>>(wq_c);
    gemm_img_k<<<gI, 256>>>(img, wk_c);
    gemm_img_v<<<gI, 256>>>(img, wv_c);
    flash_cross_kernel<<<gAtt, 256>>>();
    gemm_ao_x<<<gP, 256>>>(wo_c);                 // x += ao@wo_c

    // --- block 3: FFN ---
    ln_kernel<<<ROWS_, 256>>>(ln3_s, ln3_b);
    gemm_y_h<<<gF, 256>>>(w_ff1);                 // h = gelu(y@w_ff1)
    gemm_h_x<<<gP, 256>>>(w_ff2);                 // x += h@w_ff2

    // --- outputs: hid_new then x ---
    write_out_kernel<<<(B_*S_*D4_ + 255)/256, 256>>>(hid, out);
    copy_x_kernel<<<(ROWS_*D4_ + 255)/256, 256>>>(out + (size_t)B_*S_*D_);
}

// round 4
// speedup vs baseline: 1.3325x; 1.3325x over previous
#include <cuda_runtime.h>
#include <math.h>
#include <stdint.h>

// ---------------- problem constants (fixed instance) ----------------
#define B_ 8
#define S_ 4096
#define D_ 768
#define D4_ (D_/4)
#define NIMG_ 1024
#define FF_ 3072
#define CAP_ 640
#define H_ 12
#define DH_ 64
#define ROWS_ (B_*CAP_)      // 5120
#define IMGROWS_ (B_*NIMG_)  // 8192
#define SOC_TOK 3
#define EOS_TOK 2
#define LN_EPS 1e-5f

// weight offsets inside g_w (elements)
#define WSZ_DD (D_*D_)          // 589824
#define WOFF_FF1 (8*WSZ_DD)
#define WOFF_FF2 (WOFF_FF1 + D_*FF_)
#define WTOT (WOFF_FF2 + FF_*D_)

// ---------------- device scratch (no allocations allowed) ----------------
__device__ float g_x  [ROWS_*D_];        // running hidden x (fp32 accumulator)
__device__ float g_y  [ROWS_*D_];        // LN output (tf32-rounded fp32)
__device__ float g_q  [ROWS_*D_];        // Q projections (fp32)
__device__ float g_k  [IMGROWS_*D_];     // K projections
__device__ float g_v  [IMGROWS_*D_];     // V projections
__device__ float g_ao [ROWS_*D_];        // attention output (tf32-rounded)
__device__ float g_h  [ROWS_*FF_];       // FFN hidden (tf32-rounded)
__device__ float g_img[IMGROWS_*D_];     // img (tf32-rounded)
__device__ float g_w  [WTOT];            // all weights (tf32-rounded)
__device__ int   g_pos[B_*S_];           // slot per token, -1 if not SOC
__device__ int   g_cnt[B_];              // SOC counts per batch

// ---------------- tf32 round-to-nearest ----------------
__device__ __forceinline__ float tf32r(float x)
{
    uint32_t u;
    asm("cvt.rna.tf32.f32 %0, %1;" : "=r"(u) : "f"(x));
    return __uint_as_float(u);
}

// ---------------- conversions (fp32 -> tf32-rounded fp32) ----------------
__global__ void conv_w_kernel(const float* __restrict__ src, int off4, int n4)
{
    int i = blockIdx.x*blockDim.x + threadIdx.x;
    if (i < n4) {
        float4 v = ((const float4*)src)[i];
        v.x = tf32r(v.x); v.y = tf32r(v.y); v.z = tf32r(v.z); v.w = tf32r(v.w);
        ((float4*)g_w)[off4 + i] = v;
    }
}
__global__ void conv_img_kernel(const float* __restrict__ src)
{
    int i = blockIdx.x*blockDim.x + threadIdx.x;
    if (i < IMGROWS_*D4_) {
        float4 v = ((const float4*)src)[i];
        v.x = tf32r(v.x); v.y = tf32r(v.y); v.z = tf32r(v.z); v.w = tf32r(v.w);
        ((float4*)g_img)[i] = v;
    }
}

// ---------------- scan: soc mask + exclusive prefix ----------------
__global__ void scan_kernel(const int* __restrict__ seq)
{
    int b = blockIdx.x;
    const int* row = seq + b*S_;
    __shared__ int firstEos;
    __shared__ int wsum[32];
    if (threadIdx.x == 0) firstEos = S_;
    __syncthreads();
    for (int s = threadIdx.x; s < S_; s += blockDim.x)
        if (row[s] == EOS_TOK) atomicMin(&firstEos, s);
    __syncthreads();
    int fe = firstEos;
    int base = threadIdx.x * 4;
    int m[4]; int cnt = 0;
    #pragma unroll
    for (int i = 0; i < 4; i++) {
        int s = base + i;
        m[i] = (row[s] == SOC_TOK && s < fe) ? 1 : 0;
        cnt += m[i];
    }
    int lane = threadIdx.x & 31, w = threadIdx.x >> 5;
    int v = cnt;
    #pragma unroll
    for (int o = 1; o < 32; o <<= 1) {
        int n = __shfl_up_sync(0xffffffffu, v, o);
        if (lane >= o) v += n;
    }
    if (lane == 31) wsum[w] = v;
    __syncthreads();
    if (w == 0) {
        int t = wsum[lane];
        #pragma unroll
        for (int o = 1; o < 32; o <<= 1) {
            int n = __shfl_up_sync(0xffffffffu, t, o);
            if (lane >= o) t += n;
        }
        wsum[lane] = t;
    }
    __syncthreads();
    int excl = v - cnt + (w ? wsum[w-1] : 0);
    int* prow = g_pos + b*S_;
    #pragma unroll
    for (int i = 0; i < 4; i++) {
        prow[base+i] = m[i] ? excl : -1;
        excl += m[i];
    }
    if (threadIdx.x == 0) g_cnt[b] = wsum[31];
}

// ---------------- zero x, then gather SOC rows ----------------
__global__ void zero_x_kernel()
{
    int i = blockIdx.x*blockDim.x + threadIdx.x;
    if (i < ROWS_*D4_) ((float4*)g_x)[i] = make_float4(0.f,0.f,0.f,0.f);
}

__global__ void extract_kernel(const float* __restrict__ hid)  // grid (S_, B_), block 192
{
    int s = blockIdx.x, b = blockIdx.y;
    int p = g_pos[b*S_ + s];
    if (p < 0 || p >= CAP_) return;
    const float4* src = (const float4*)(hid + ((size_t)(b*S_+s))*D_);
    float4* dst = (float4*)(g_x + ((size_t)(b*CAP_+p))*D_);
    dst[threadIdx.x] = src[threadIdx.x];
}

// ---------------- LayerNorm: g_x -> g_y (tf32-rounded) ----------------
__global__ void ln_kernel(const float* __restrict__ sc, const float* __restrict__ bi)
{
    int r = blockIdx.x;
    const float* x = g_x + (size_t)r*D_;
    float s1 = 0.f, s2 = 0.f;
    for (int d = threadIdx.x; d < D_; d += blockDim.x) {
        float v = x[d]; s1 += v; s2 += v*v;
    }
    #pragma unroll
    for (int o = 16; o > 0; o >>= 1) {
        s1 += __shfl_xor_sync(0xffffffffu, s1, o);
        s2 += __shfl_xor_sync(0xffffffffu, s2, o);
    }
    __shared__ float a1[8], a2[8];
    int w = threadIdx.x >> 5, l = threadIdx.x & 31;
    if (l == 0) { a1[w] = s1; a2[w] = s2; }
    __syncthreads();
    if (threadIdx.x == 0) {
        float t1 = 0.f, t2 = 0.f;
        #pragma unroll
        for (int i = 0; i < 8; i++) { t1 += a1[i]; t2 += a2[i]; }
        a1[0] = t1; a2[0] = t2;
    }
    __syncthreads();
    float mu  = a1[0] * (1.f/(float)D_);
    float var = a2[0] * (1.f/(float)D_) - mu*mu;
    float rs  = rsqrtf(var + LN_EPS);
    float* o = g_y + (size_t)r*D_;
    for (int d = threadIdx.x; d < D_; d += blockDim.x)
        o[d] = tf32r((x[d]-mu)*rs*sc[d] + bi[d]);
}

// ---------------- GELU ----------------
__device__ __forceinline__ float gelu_f(float v)
{
    const float c = 0.7978845608028654f;   // sqrt(2/pi)
    float inner = c*(v + 0.044715f*v*v*v);
    return 0.5f*v*(1.f + tanhf(inner));
}

// ---------------- cp.async primitives ----------------
__device__ __forceinline__ uint32_t smem_u32(const void* p)
{
    return (uint32_t)__cvta_generic_to_shared(p);
}
__device__ __forceinline__ void cp16(uint32_t dst, const void* src)
{
    asm volatile("cp.async.cg.shared.global [%0], [%1], 16;" :: "r"(dst), "l"(src));
}
__device__ __forceinline__ void cp_commit() { asm volatile("cp.async.commit_group;"); }
__device__ __forceinline__ void cp_wait1()  { asm volatile("cp.async.wait_group 1;"); }
__device__ __forceinline__ void cp_wait0()  { asm volatile("cp.async.wait_group 0;"); }

// ---------------- tf32 mma m16n8k8 ----------------
__device__ __forceinline__ void mma_tf32(float* c, const uint32_t* a, uint32_t b0, uint32_t b1)
{
    asm volatile("mma.sync.aligned.m16n8k8.row.col.f32.tf32.tf32.f32 "
        "{%0,%1,%2,%3}, {%4,%5,%6,%7}, {%8,%9}, {%0,%1,%2,%3};"
        : "+f"(c[0]),"+f"(c[1]),"+f"(c[2]),"+f"(c[3])
        : "r"(a[0]),"r"(a[1]),"r"(a[2]),"r"(a[3]), "r"(b0),"r"(b1));
}

// ---------------- tf32 tensor-core GEMM: C[M,N] (+)= A[M,K] @ W[K,N] ----------------
// BM=128 BN=128 BK=16, 256 threads = 8 warps (2 M x 4 N), warp tile 64x32.
// OUTMODE: 0 = store fp32, 1 = accumulate fp32, 2 = gelu -> tf32-rounded fp32
#define BM 128
#define BN 128
#define BK 16
#define ASTR 20    // words per A smem row (16 + 4 pad): lane addr g*20+t distinct mod 32
#define BSTR 136   // words per B smem row (128 + 8 pad): lane addr t*8+g distinct mod 32

template<int OUTMODE>
__device__ __forceinline__ void tgemm_body(
    const float* __restrict__ A, const float* __restrict__ W,
    float* __restrict__ C, int N, int K)
{
    __shared__ float As[2][BM*ASTR];
    __shared__ float Bs[2][BK*BSTR];

    const int tid  = threadIdx.x;
    const int bm   = blockIdx.y*BM, bn = blockIdx.x*BN;
    const int warp = tid >> 5, lane = tid & 31;
    const int wm   = (warp >> 2)*64;     // warp row offset
    const int wn   = (warp & 3)*32;      // warp col offset
    const int g    = lane >> 2, t = lane & 3;

    float acc[4][4][4];
    #pragma unroll
    for (int i = 0; i < 4; i++)
        #pragma unroll
        for (int j = 0; j < 4; j++)
            #pragma unroll
            for (int r = 0; r < 4; r++) acc[i][j][r] = 0.f;

    // global load mapping (per thread: A 2x16B, B 2x16B)
    const int ar = tid >> 2;            // 0..63 (also ar+64)
    const int ac = (tid & 3)*4;         // float offset in row
    const int br = tid >> 4;            // 0..15
    const int bc = (tid & 15)*8;        // float offset in row

    const float* Ap  = A + (size_t)(bm + ar)*K + ac;
    const float* Ap2 = A + (size_t)(bm + ar + 64)*K + ac;
    const float* Bp  = W + (size_t)br*N + bn + bc;

    uint32_t aDst[2], bDst[2];
    #pragma unroll
    for (int u = 0; u < 2; u++) {
        aDst[u] = smem_u32(&As[u][ar*ASTR + ac]);
        bDst[u] = smem_u32(&Bs[u][br*BSTR + bc]);
    }

    const int nt = K / BK;
    // prologue: prefetch tile 0 -> buf 0
    cp16(aDst[0],              Ap);
    cp16(aDst[0] + 64*ASTR*4,  Ap2);
    cp16(bDst[0],              Bp);
    cp16(bDst[0] + 16,         Bp + 4);
    cp_commit();

    for (int it = 0; it < nt; it++) {
        const int cur = it & 1, nxt = cur ^ 1;
        if (it + 1 < nt) {
            const int k0 = (it + 1)*BK;
            cp16(aDst[nxt],             Ap + k0);
            cp16(aDst[nxt] + 64*ASTR*4, Ap2 + k0);
            cp16(bDst[nxt],             Bp + (size_t)k0*N);
            cp16(bDst[nxt] + 16,        Bp + (size_t)k0*N + 4);
            cp_commit();
            cp_wait1();
        } else {
            cp_wait0();
        }
        __syncthreads();

        const float* Ab = As[cur];
        const float* Bb = Bs[cur];
        #pragma unroll
        for (int kc = 0; kc < 2; kc++) {
            const int kk = kc*8;
            uint32_t af[4][4];
            #pragma unroll
            for (int i = 0; i < 4; i++) {
                const int rb = wm + i*16;
                af[i][0] = __float_as_uint(Ab[(rb + g    )*ASTR + kk + t    ]);
                af[i][1] = __float_as_uint(Ab[(rb + 8 + g)*ASTR + kk + t    ]);
                af[i][2] = __float_as_uint(Ab[(rb + g    )*ASTR + kk + t + 4]);
                af[i][3] = __float_as_uint(Ab[(rb + 8 + g)*ASTR + kk + t + 4]);
            }
            uint32_t bfv[4][2];
            #pragma unroll
            for (int j = 0; j < 4; j++) {
                const int cbn = wn + j*8 + g;
                bfv[j][0] = __float_as_uint(Bb[(kk + t    )*BSTR + cbn]);
                bfv[j][1] = __float_as_uint(Bb[(kk + t + 4)*BSTR + cbn]);
            }
            #pragma unroll
            for (int i = 0; i < 4; i++)
                #pragma unroll
                for (int j = 0; j < 4; j++)
                    mma_tf32(acc[i][j], af[i], bfv[j][0], bfv[j][1]);
        }
        __syncthreads();
    }

    // epilogue: c0=(g,2t) c1=(g,2t+1) c2=(g+8,2t) c3=(g+8,2t+1)
    #pragma unroll
    for (int i = 0; i < 4; i++) {
        const int row0 = bm + wm + i*16 + g;
        #pragma unroll
        for (int j = 0; j < 4; j++) {
            const int col = bn + wn + j*8 + t*2;
            float* c = acc[i][j];
            float* p0 = &C[(size_t)row0*N + col];
            float* p1 = &C[(size_t)(row0+8)*N + col];
            if (OUTMODE == 2) {
                *(float2*)p0 = make_float2(tf32r(gelu_f(c[0])), tf32r(gelu_f(c[1])));
                *(float2*)p1 = make_float2(tf32r(gelu_f(c[2])), tf32r(gelu_f(c[3])));
            } else if (OUTMODE == 1) {
                float2 o0 = *(float2*)p0, o1 = *(float2*)p1;
                *(float2*)p0 = make_float2(o0.x + c[0], o0.y + c[1]);
                *(float2*)p1 = make_float2(o1.x + c[2], o1.y + c[3]);
            } else {
                *(float2*)p0 = make_float2(c[0], c[1]);
                *(float2*)p1 = make_float2(c[2], c[3]);
            }
        }
    }
}

// GEMM wrapper kernels
__global__ void __launch_bounds__(256,2) gemm_yq (int wo){ tgemm_body<0>(g_y,   g_w+wo, g_q, D_,  D_ ); }
__global__ void __launch_bounds__(256,2) gemm_yk (int wo){ tgemm_body<0>(g_y,   g_w+wo, g_k, D_,  D_ ); }
__global__ void __launch_bounds__(256,2) gemm_yv (int wo){ tgemm_body<0>(g_y,   g_w+wo, g_v, D_,  D_ ); }
__global__ void __launch_bounds__(256,2) gemm_ik (int wo){ tgemm_body<0>(g_img, g_w+wo, g_k, D_,  D_ ); }
__global__ void __launch_bounds__(256,2) gemm_iv (int wo){ tgemm_body<0>(g_img, g_w+wo, g_v, D_,  D_ ); }
__global__ void __launch_bounds__(256,2) gemm_ao (int wo){ tgemm_body<1>(g_ao,  g_w+wo, g_x, D_,  D_ ); }
__global__ void __launch_bounds__(256,2) gemm_ff1(int wo){ tgemm_body<2>(g_y,   g_w+wo, g_h, FF_, D_ ); }
__global__ void __launch_bounds__(256,2) gemm_ff2(int wo){ tgemm_body<1>(g_h,   g_w+wo, g_x, D_,  FF_); }

// ---------------- flash attention (fp32, online softmax), tf32-rounded out ----------------
template<bool MASK>
__device__ __forceinline__ void flash_body(int Lk)
{
    const int q0 = blockIdx.x * 64;
    const int h  = blockIdx.y;
    const int b  = blockIdx.z;
    const int tid = threadIdx.x;
    const int qi = tid >> 2;
    const int g  = tid & 3;

    __shared__ float Ks[64][68];
    __shared__ float Vs[64][68];
    float (*Ps)[68] = Ks;          // P tile reuses K tile storage

    float qreg[DH_];
    {
        const float* qp = g_q + ((size_t)(b*CAP_ + q0 + qi))*D_ + h*DH_;
        #pragma unroll
        for (int i = 0; i < DH_/4; i++) {
            float4 t = *(const float4*)(qp + 4*i);
            qreg[4*i]=t.x; qreg[4*i+1]=t.y; qreg[4*i+2]=t.z; qreg[4*i+3]=t.w;
        }
    }
    float Oacc[16];
    #pragma unroll
    for (int t = 0; t < 16; t++) Oacc[t] = 0.f;
    float mrun = -1e30f, lrun = 0.f;
    const int cnt = MASK ? g_cnt[b] : Lk;

    const int kr = tid >> 2;
    const int cb = (tid & 3) * 16;

    for (int k0 = 0; k0 < Lk; k0 += 64) {
        const float* kp = g_k + ((size_t)(b*Lk + k0 + kr))*D_ + h*DH_ + cb;
        const float* vp = g_v + ((size_t)(b*Lk + k0 + kr))*D_ + h*DH_ + cb;
        #pragma unroll
        for (int i = 0; i < 4; i++) {
            *(float4*)&Ks[kr][cb + 4*i] = *(const float4*)(kp + 4*i);
            *(float4*)&Vs[kr][cb + 4*i] = *(const float4*)(vp + 4*i);
        }
        __syncthreads();
        float s[16];
        #pragma unroll
        for (int j = 0; j < 16; j++) {
            int kj = 4*j + g;
            const float* krow = &Ks[kj][0];
            float acc = 0.f;
            #pragma unroll
            for (int d = 0; d < DH_; d += 4) {
                float4 kv = *(const float4*)(krow + d);
                acc = fmaf(qreg[d],   kv.x, acc);
                acc = fmaf(qreg[d+1], kv.y, acc);
                acc = fmaf(qreg[d+2], kv.z, acc);
                acc = fmaf(qreg[d+3], kv.w, acc);
            }
            acc *= 0.125f;  // 1/sqrt(64)
            if (MASK && (k0 + kj) >= cnt) acc = -1e9f;
            s[j] = acc;
        }
        float mx = s[0];
        #pragma unroll
        for (int j = 1; j < 16; j++) mx = fmaxf(mx, s[j]);
        mx = fmaxf(mx, __shfl_xor_sync(0xffffffffu, mx, 1));
        mx = fmaxf(mx, __shfl_xor_sync(0xffffffffu, mx, 2));
        float mnew = fmaxf(mrun, mx);
        float corr = expf(mrun - mnew);
        float lsum = 0.f;
        #pragma unroll
        for (int j = 0; j < 16; j++) { float p = expf(s[j]-mnew); s[j] = p; lsum += p; }
        lsum += __shfl_xor_sync(0xffffffffu, lsum, 1);
        lsum += __shfl_xor_sync(0xffffffffu, lsum, 2);
        lrun = lrun*corr + lsum;
        mrun = mnew;
        __syncthreads();
        #pragma unroll
        for (int j = 0; j < 16; j++) Ps[qi][4*j+g] = s[j];
        #pragma unroll
        for (int t = 0; t < 16; t++) Oacc[t] *= corr;
        __syncthreads();
        #pragma unroll
        for (int kk = 0; kk < 64; kk += 4) {
            float4 p4 = *(const float4*)&Ps[qi][kk];
            float pv[4] = {p4.x, p4.y, p4.z, p4.w};
            #pragma unroll
            for (int u = 0; u < 4; u++) {
                const float* vrow = &Vs[kk+u][cb];
                #pragma unroll
                for (int t = 0; t < 16; t += 4) {
                    float4 vv = *(const float4*)(vrow + t);
                    Oacc[t]   = fmaf(pv[u], vv.x, Oacc[t]);
                    Oacc[t+1] = fmaf(pv[u], vv.y, Oacc[t+1]);
                    Oacc[t+2] = fmaf(pv[u], vv.z, Oacc[t+2]);
                    Oacc[t+3] = fmaf(pv[u], vv.w, Oacc[t+3]);
                }
            }
        }
        __syncthreads();
    }
    float inv = 1.f / lrun;
    float* op = g_ao + ((size_t)(b*CAP_ + q0 + qi))*D_ + h*DH_ + cb;
    #pragma unroll
    for (int t = 0; t < 16; t += 2)
        *(float2*)(op + t) = make_float2(tf32r(Oacc[t]*inv), tf32r(Oacc[t+1]*inv));
}

__global__ void __launch_bounds__(256) flash_self_kernel () { flash_body<true >(CAP_);  }
__global__ void __launch_bounds__(256) flash_cross_kernel() { flash_body<false>(NIMG_); }

// ---------------- outputs ----------------
__global__ void write_out_kernel(const float* __restrict__ hid, float* __restrict__ out)
{
    int i = blockIdx.x*blockDim.x + threadIdx.x;
    if (i >= B_*S_*D4_) return;
    int row = i / D4_;
    int d4  = i - row*D4_;
    int p = g_pos[row];
    float4 v;
    if (p >= 0) {
        int b = row >> 12;                  // row / S_
        int q = p < CAP_ ? p : (CAP_-1);    // reference clips idx to cap-1
        v = ((const float4*)g_x)[(size_t)(b*CAP_+q)*D4_ + d4];
    } else {
        v = ((const float4*)hid)[i];
    }
    ((float4*)out)[i] = v;
}

__global__ void copy_x_kernel(float* __restrict__ out)
{
    int i = blockIdx.x*blockDim.x + threadIdx.x;
    if (i < ROWS_*D4_) ((float4*)out)[i] = ((const float4*)g_x)[i];
}

// ---------------- launch: pure kernel launches ----------------
extern "C" void kernel_launch(void* const* d_in, const int* in_sizes, int n_in,
                              void* d_out, int out_size)
{
    const float* img   = (const float*)d_in[0];
    const float* hid   = (const float*)d_in[1];
    const int*   seq   = (const int*)  d_in[2];
    const float* wq_s  = (const float*)d_in[3];
    const float* wk_s  = (const float*)d_in[4];
    const float* wv_s  = (const float*)d_in[5];
    const float* wo_s  = (const float*)d_in[6];
    const float* wq_c  = (const float*)d_in[7];
    const float* wk_c  = (const float*)d_in[8];
    const float* wv_c  = (const float*)d_in[9];
    const float* wo_c  = (const float*)d_in[10];
    const float* w_ff1 = (const float*)d_in[11];
    const float* w_ff2 = (const float*)d_in[12];
    const float* ln1_s = (const float*)d_in[13];
    const float* ln1_b = (const float*)d_in[14];
    const float* ln2_s = (const float*)d_in[15];
    const float* ln2_b = (const float*)d_in[16];
    const float* ln3_s = (const float*)d_in[17];
    const float* ln3_b = (const float*)d_in[18];
    float* out = (float*)d_out;

    // ---- tf32 rounding of weights + img ----
    {
        const int n4dd = WSZ_DD/4;
        const int gdd = (n4dd + 255)/256;
        conv_w_kernel<<<gdd, 256>>>(wq_s, 0*n4dd, n4dd);
        conv_w_kernel<<<gdd, 256>>>(wk_s, 1*n4dd, n4dd);
        conv_w_kernel<<<gdd, 256>>>(wv_s, 2*n4dd, n4dd);
        conv_w_kernel<<<gdd, 256>>>(wo_s, 3*n4dd, n4dd);
        conv_w_kernel<<<gdd, 256>>>(wq_c, 4*n4dd, n4dd);
        conv_w_kernel<<<gdd, 256>>>(wk_c, 5*n4dd, n4dd);
        conv_w_kernel<<<gdd, 256>>>(wv_c, 6*n4dd, n4dd);
        conv_w_kernel<<<gdd, 256>>>(wo_c, 7*n4dd, n4dd);
        const int n4ff = D_*FF_/4;
        const int gff = (n4ff + 255)/256;
        conv_w_kernel<<<gff, 256>>>(w_ff1, WOFF_FF1/4, n4ff);
        conv_w_kernel<<<gff, 256>>>(w_ff2, WOFF_FF2/4, n4ff);
        conv_img_kernel<<<(IMGROWS_*D4_ + 255)/256, 256>>>(img);
    }

    // ---- mask + extract ----
    scan_kernel<<<B_, 1024>>>(seq);
    zero_x_kernel<<<(ROWS_*D4_ + 255)/256, 256>>>();
    extract_kernel<<<dim3(S_, B_), 192>>>(hid);

    dim3 gP(D_/BN, ROWS_/BM);       // 6 x 40
    dim3 gI(D_/BN, IMGROWS_/BM);    // 6 x 64
    dim3 gF(FF_/BN, ROWS_/BM);      // 24 x 40
    dim3 gAtt(CAP_/64, H_, B_);     // 10 x 12 x 8

    // --- block 1: self-attention ---
    ln_kernel<<<ROWS_, 256>>>(ln1_s, ln1_b);
    gemm_yq<<<gP, 256>>>(0*WSZ_DD);
    gemm_yk<<<gP, 256>>>(1*WSZ_DD);
    gemm_yv<<<gP, 256>>>(2*WSZ_DD);
    flash_self_kernel<<<gAtt, 256>>>();
    gemm_ao<<<gP, 256>>>(3*WSZ_DD);               // x += ao@wo_s

    // --- block 2: cross-attention to img ---
    ln_kernel<<<ROWS_, 256>>>(ln2_s, ln2_b);
    gemm_yq<<<gP, 256>>>(4*WSZ_DD);
    gemm_ik<<<gI, 256>>>(5*WSZ_DD);
    gemm_iv<<<gI, 256>>>(6*WSZ_DD);
    flash_cross_kernel<<<gAtt, 256>>>();
    gemm_ao<<<gP, 256>>>(7*WSZ_DD);               // x += ao@wo_c

    // --- block 3: FFN ---
    ln_kernel<<<ROWS_, 256>>>(ln3_s, ln3_b);
    gemm_ff1<<<gF, 256>>>(WOFF_FF1);              // h = gelu(y@w_ff1), tf32
    gemm_ff2<<<gP, 256>>>(WOFF_FF2);              // x += h@w_ff2

    // --- outputs: hid_new then x ---
    write_out_kernel<<<(B_*S_*D4_ + 255)/256, 256>>>(hid, out);
    copy_x_kernel<<<(ROWS_*D4_ + 255)/256, 256>>>(out + (size_t)B_*S_*D_);
}